// round 2
// baseline (speedup 1.0000x reference)
#include <cuda_runtime.h>
#include <math.h>

#define H 1024
#define H4 256          // H/4
#define V 50000
#define E 602
#define S 400
#define NCHUNK 16       // s-chunks for attention partials
#define SPC 25          // S / NCHUNK
#define NLOGBLK 3125    // V / 16 rows per block

// ---------------- scratch (static device globals; no allocs) ----------------
__device__ float g_hnew[H];
__device__ float g_q[H];
__device__ float g_scores[S];
__device__ float g_attnw[S];
__device__ float g_attn_part[NCHUNK][H];
__device__ float g_pg_part[NCHUNK][E];
__device__ float g_attn_applied[H];
__device__ float g_log_pgen;
__device__ float g_ff[H];
__device__ float g_logits[V];
__device__ float g_maxpart[NLOGBLK];
__device__ float g_logc;

// ---------------- helpers ----------------
__device__ __forceinline__ float warpReduceSum(float v) {
#pragma unroll
    for (int o = 16; o > 0; o >>= 1) v += __shfl_xor_sync(0xffffffffu, v, o);
    return v;
}
__device__ __forceinline__ float warpReduceMax(float v) {
#pragma unroll
    for (int o = 16; o > 0; o >>= 1) v = fmaxf(v, __shfl_xor_sync(0xffffffffu, v, o));
    return v;
}

__device__ __forceinline__ float blockReduceSum(float v) {
    __shared__ float sh[33];
    __syncthreads();
    int lane = threadIdx.x & 31, wid = threadIdx.x >> 5;
    v = warpReduceSum(v);
    if (lane == 0) sh[wid] = v;
    __syncthreads();
    int nw = (blockDim.x + 31) >> 5;
    float r = (threadIdx.x < nw) ? sh[threadIdx.x] : 0.f;
    if (wid == 0) {
        r = warpReduceSum(r);
        if (lane == 0) sh[32] = r;
    }
    __syncthreads();
    return sh[32];
}

__device__ __forceinline__ float blockReduceMax(float v) {
    __shared__ float sh[33];
    __syncthreads();
    int lane = threadIdx.x & 31, wid = threadIdx.x >> 5;
    v = warpReduceMax(v);
    if (lane == 0) sh[wid] = v;
    __syncthreads();
    int nw = (blockDim.x + 31) >> 5;
    float r = (threadIdx.x < nw) ? sh[threadIdx.x] : -3.4e38f;
    if (wid == 0) {
        r = warpReduceMax(r);
        if (lane == 0) sh[32] = r;
    }
    __syncthreads();
    return sh[32];
}

// dot of two length-(4*n4) fp32 vectors across a warp; result on all lanes
__device__ __forceinline__ float warp_dot4(const float* __restrict__ a,
                                           const float* __restrict__ b, int n4) {
    const float4* a4 = reinterpret_cast<const float4*>(a);
    const float4* b4 = reinterpret_cast<const float4*>(b);
    int lane = threadIdx.x & 31;
    float s = 0.f;
    for (int k = lane; k < n4; k += 32) {
        float4 x = __ldg(a4 + k);
        float4 y = __ldg(b4 + k);
        s = fmaf(x.x, y.x, fmaf(x.y, y.y, fmaf(x.z, y.z, fmaf(x.w, y.w, s))));
    }
    return warpReduceSum(s);
}

__device__ __forceinline__ float sigmoidf_(float x) { return 1.f / (1.f + expf(-x)); }

// ---------------- K1: fused GRU step -> g_hnew ----------------
__global__ void k_gru(const int* __restrict__ idx,
                      const float* __restrict__ hidden,
                      const float* __restrict__ trigger,
                      const float* __restrict__ emb,
                      const float* __restrict__ W_ih,
                      const float* __restrict__ W_hh,
                      const float* __restrict__ b_ih,
                      const float* __restrict__ b_hh) {
    int w = (blockIdx.x * blockDim.x + threadIdx.x) >> 5;
    if (w >= H) return;
    const float* erow = emb + (size_t)idx[0] * H;
    // x = [embedded, trigger]
    const float* ri = W_ih + (size_t)w * 2 * H;
    const float* zi = W_ih + (size_t)(H + w) * 2 * H;
    const float* ni = W_ih + (size_t)(2 * H + w) * 2 * H;
    float gi_r = warp_dot4(ri, erow, H4) + warp_dot4(ri + H, trigger, H4);
    float gi_z = warp_dot4(zi, erow, H4) + warp_dot4(zi + H, trigger, H4);
    float gi_n = warp_dot4(ni, erow, H4) + warp_dot4(ni + H, trigger, H4);
    float gh_r = warp_dot4(W_hh + (size_t)w * H, hidden, H4);
    float gh_z = warp_dot4(W_hh + (size_t)(H + w) * H, hidden, H4);
    float gh_n = warp_dot4(W_hh + (size_t)(2 * H + w) * H, hidden, H4);
    if ((threadIdx.x & 31) == 0) {
        float r = sigmoidf_(gi_r + b_ih[w] + gh_r + b_hh[w]);
        float z = sigmoidf_(gi_z + b_ih[H + w] + gh_z + b_hh[H + w]);
        float n = tanhf(gi_n + b_ih[2 * H + w] + r * (gh_n + b_hh[2 * H + w]));
        g_hnew[w] = (1.f - z) * n + z * hidden[w];
    }
}

// ---------------- K2: q = attn_W @ h_new ----------------
__global__ void k_q(const float* __restrict__ attn_W) {
    int w = (blockIdx.x * blockDim.x + threadIdx.x) >> 5;
    if (w >= H) return;
    float v = warp_dot4(attn_W + (size_t)w * H, g_hnew, H4);
    if ((threadIdx.x & 31) == 0) g_q[w] = v;
}

// ---------------- K3: scores = enc @ q ----------------
__global__ void k_scores(const float* __restrict__ enc) {
    int w = (blockIdx.x * blockDim.x + threadIdx.x) >> 5;
    if (w >= S) return;
    float v = warp_dot4(enc + (size_t)w * H, g_q, H4);
    if ((threadIdx.x & 31) == 0) g_scores[w] = v;
}

// ---------------- K4: softmax over S=400 (one block) ----------------
__global__ void k_softmax_s() {
    int t = threadIdx.x;
    float v = (t < S) ? g_scores[t] : -3.4e38f;
    float m = blockReduceMax(v);
    float e = (t < S) ? expf(v - m) : 0.f;
    float sum = blockReduceSum(e);
    if (t < S) g_attnw[t] = e / sum;
}

// ---------------- K5: partial attn_applied + pg accumulation ----------------
__global__ void k_attn_part(const float* __restrict__ enc,
                            const float* __restrict__ pg_mat) {
    int c = blockIdx.x;     // chunk of s
    int j = threadIdx.x;    // 0..1023
    __shared__ float ws[SPC];
    if (j < SPC) ws[j] = g_attnw[c * SPC + j];
    __syncthreads();
    float acc = 0.f, accp = 0.f;
#pragma unroll 5
    for (int k = 0; k < SPC; k++) {
        int s = c * SPC + k;
        float w = ws[k];
        acc = fmaf(w, __ldg(enc + (size_t)s * H + j), acc);
        if (j < E) accp = fmaf(w, __ldg(pg_mat + (size_t)s * E + j), accp);
    }
    g_attn_part[c][j] = acc;
    if (j < E) g_pg_part[c][j] = accp;
}

// ---------------- K6: finish attention, p_gen, write small outputs ----------
__global__ void k_attn_finish(const int* __restrict__ idx,
                              const float* __restrict__ emb,
                              const float* __restrict__ wh_W,
                              const float* __restrict__ ws_W,
                              const float* __restrict__ wx_W,
                              const float* __restrict__ wx_b,
                              float* __restrict__ out, int out_size) {
    int j = threadIdx.x;    // 1024 threads
    float a = 0.f;
#pragma unroll
    for (int c = 0; c < NCHUNK; c++) a += g_attn_part[c][j];
    g_attn_applied[j] = a;
    float p = 0.f;
    if (j < E) {
#pragma unroll
        for (int c = 0; c < NCHUNK; c++) p += g_pg_part[c][j];
    }
    const float* erow = emb + (size_t)idx[0] * H;
    float val = __ldg(wh_W + j) * a + __ldg(ws_W + j) * g_hnew[j] + __ldg(wx_W + j) * erow[j];
    float t = blockReduceSum(val);
    __shared__ float pgen_s;
    if (j == 0) {
        float pg = sigmoidf_(t + wx_b[0]);
        pgen_s = pg;
        g_log_pgen = logf(pg);
    }
    __syncthreads();
    float pgen = pgen_s;
    // outputs: [0,V+E) logprobs | [V+E, V+E+H) h_new | [V+E+H, +S) attn_weights
    if (j < E && (V + j) < out_size) out[V + j] = logf(p * (1.f - pgen));
    if ((V + E + j) < out_size) out[V + E + j] = g_hnew[j];
    if (j < S && (V + E + H + j) < out_size) out[V + E + H + j] = g_attnw[j];
}

// ---------------- K7: ff = relu(comb_W @ [h_new, attn_applied] + b) --------
__global__ void k_ff(const float* __restrict__ comb_W,
                     const float* __restrict__ comb_b) {
    int w = (blockIdx.x * blockDim.x + threadIdx.x) >> 5;
    if (w >= H) return;
    const float* row = comb_W + (size_t)w * 2 * H;
    float v = warp_dot4(row, g_hnew, H4) + warp_dot4(row + H, g_attn_applied, H4);
    if ((threadIdx.x & 31) == 0) g_ff[w] = fmaxf(v + comb_b[w], 0.f);
}

// ---------------- K8: logits + per-block max partial (16 warps/block) -------
__global__ void k_logits(const float* __restrict__ out_W,
                         const float* __restrict__ out_b) {
    int wi = threadIdx.x >> 5;
    int j = blockIdx.x * 16 + wi;       // always < V (3125*16)
    float l = warp_dot4(out_W + (size_t)j * H, g_ff, H4) + __ldg(out_b + j);
    __shared__ float sm16[16];
    if ((threadIdx.x & 31) == 0) {
        g_logits[j] = l;
        sm16[wi] = l;
    }
    __syncthreads();
    if (threadIdx.x == 0) {
        float m = sm16[0];
#pragma unroll
        for (int k = 1; k < 16; k++) m = fmaxf(m, sm16[k]);
        g_maxpart[blockIdx.x] = m;
    }
}

// ---------------- K9: fused global max + logsumexp + combine log(p_gen) ----
__global__ void k_lse() {
    // global max over block partials
    float m = -3.4e38f;
    for (int k = threadIdx.x; k < NLOGBLK; k += blockDim.x) m = fmaxf(m, g_maxpart[k]);
    float gm = blockReduceMax(m);
    // logsumexp over V
    float s = 0.f;
    for (int k = threadIdx.x; k < V; k += blockDim.x) s += expf(g_logits[k] - gm);
    s = blockReduceSum(s);
    if (threadIdx.x == 0) g_logc = gm + logf(s) - g_log_pgen;
}

// ---------------- K10: final vocab log-probs ----------------
__global__ void k_vocab_out(float* __restrict__ out) {
    int j = blockIdx.x * blockDim.x + threadIdx.x;
    if (j < V) out[j] = g_logits[j] - g_logc;
}

// ---------------- launch ----------------
extern "C" void kernel_launch(void* const* d_in, const int* in_sizes, int n_in,
                              void* d_out, int out_size) {
    const int*   idx     = (const int*)  d_in[0];
    const float* hidden  = (const float*)d_in[1];
    const float* enc     = (const float*)d_in[2];
    const float* trigger = (const float*)d_in[3];
    const float* pg_mat  = (const float*)d_in[4];
    const float* emb     = (const float*)d_in[5];
    const float* attn_W  = (const float*)d_in[6];
    const float* comb_W  = (const float*)d_in[7];
    const float* comb_b  = (const float*)d_in[8];
    const float* W_ih    = (const float*)d_in[9];
    const float* W_hh    = (const float*)d_in[10];
    const float* b_ih    = (const float*)d_in[11];
    const float* b_hh    = (const float*)d_in[12];
    const float* out_W   = (const float*)d_in[13];
    const float* out_b   = (const float*)d_in[14];
    const float* wh_W    = (const float*)d_in[15];
    const float* ws_W    = (const float*)d_in[16];
    const float* wx_W    = (const float*)d_in[17];
    const float* wx_b    = (const float*)d_in[18];
    float* out = (float*)d_out;

    (void)in_sizes; (void)n_in;

    k_gru<<<128, 256>>>(idx, hidden, trigger, emb, W_ih, W_hh, b_ih, b_hh);
    k_q<<<128, 256>>>(attn_W);
    k_scores<<<50, 256>>>(enc);
    k_softmax_s<<<1, 512>>>();
    k_attn_part<<<NCHUNK, 1024>>>(enc, pg_mat);
    k_attn_finish<<<1, 1024>>>(idx, emb, wh_W, ws_W, wx_W, wx_b, out, out_size);
    k_ff<<<128, 256>>>(comb_W, comb_b);
    k_logits<<<NLOGBLK, 512>>>(out_W, out_b);
    k_lse<<<1, 1024>>>();
    k_vocab_out<<<196, 256>>>(out);
}

// round 4
// speedup vs baseline: 1.3936x; 1.3936x over previous
#include <cuda_runtime.h>
#include <math.h>

#define H 1024
#define H4 256          // H/4 (float4 count)
#define V 50000
#define E 602
#define S 400
#define NB 148          // blocks == SMs (B200)
#define TPB 512
#define NWARP 16        // TPB/32
#define GWARPS (NB*NWARP)   // 2368
#define NCHUNK 16
#define SPC 25          // S / NCHUNK

// ---------------- scratch (static device globals; no allocs) ----------------
__device__ float g_gi[3*H];
__device__ float g_gh[3*H];
__device__ float g_q[H];
__device__ float g_scores[S];
__device__ float g_attn_part[NCHUNK][H];
__device__ float g_pg_part[NCHUNK][E];
__device__ float g_ff[H];
__device__ float g_logits[V];
__device__ float g_maxpart[NB];
__device__ float g_sumpart[NB];
__device__ volatile unsigned g_flags[NB];   // zero-initialized; monotonic across replays

// ---------------- helpers ----------------
__device__ __forceinline__ float warpReduceSum(float v) {
#pragma unroll
    for (int o = 16; o > 0; o >>= 1) v += __shfl_xor_sync(0xffffffffu, v, o);
    return v;
}
__device__ __forceinline__ float warpReduceMax(float v) {
#pragma unroll
    for (int o = 16; o > 0; o >>= 1) v = fmaxf(v, __shfl_xor_sync(0xffffffffu, v, o));
    return v;
}
__device__ __forceinline__ float blockReduceSum(float v) {
    __shared__ float sh[33];
    __syncthreads();
    int lane = threadIdx.x & 31, wid = threadIdx.x >> 5;
    v = warpReduceSum(v);
    if (lane == 0) sh[wid] = v;
    __syncthreads();
    float r = (threadIdx.x < NWARP) ? sh[threadIdx.x] : 0.f;
    if (wid == 0) {
        r = warpReduceSum(r);
        if (lane == 0) sh[32] = r;
    }
    __syncthreads();
    return sh[32];
}
__device__ __forceinline__ float blockReduceMax(float v) {
    __shared__ float sh[33];
    __syncthreads();
    int lane = threadIdx.x & 31, wid = threadIdx.x >> 5;
    v = warpReduceMax(v);
    if (lane == 0) sh[wid] = v;
    __syncthreads();
    float r = (threadIdx.x < NWARP) ? sh[threadIdx.x] : -3.4e38f;
    if (wid == 0) {
        r = warpReduceMax(r);
        if (lane == 0) sh[32] = r;
    }
    __syncthreads();
    return sh[32];
}

// warp-collective dot of 4*n4 floats; result broadcast to all lanes.
// b may be global or shared (generic pointer). n4 is compile-time -> fully unrolled.
__device__ __forceinline__ float warp_dot4(const float* __restrict__ a,
                                           const float* __restrict__ b, int n4) {
    const float4* a4 = reinterpret_cast<const float4*>(a);
    const float4* b4 = reinterpret_cast<const float4*>(b);
    int lane = threadIdx.x & 31;
    float s = 0.f;
#pragma unroll 8
    for (int k = lane; k < n4; k += 32) {
        float4 x = a4[k];
        float4 y = b4[k];
        s = fmaf(x.x, y.x, fmaf(x.y, y.y, fmaf(x.z, y.z, fmaf(x.w, y.w, s))));
    }
    return warpReduceSum(s);
}

__device__ __forceinline__ float sigmoidf_(float x) { return 1.f / (1.f + expf(-x)); }

// flat grid barrier: each block publishes its own monotonic flag; 148 threads
// poll one flag each. Flags persist across graph replays (each block reads only
// its OWN flag at entry, which only itself writes -> race-free).
__device__ __forceinline__ void grid_bar(unsigned myflag) {
    __syncthreads();
    if (threadIdx.x == 0) {
        __threadfence();
        g_flags[blockIdx.x] = myflag;
    }
    if (threadIdx.x < NB) {
        while (g_flags[threadIdx.x] < myflag) { }
    }
    __syncthreads();
}

// ---------------- the single persistent kernel ----------------
__global__ void __launch_bounds__(TPB, 1)
decoder_step(const int* __restrict__ idx,
             const float* __restrict__ hidden,
             const float* __restrict__ enc,
             const float* __restrict__ trigger,
             const float* __restrict__ pg_mat,
             const float* __restrict__ emb,
             const float* __restrict__ attn_W,
             const float* __restrict__ comb_W,
             const float* __restrict__ comb_b,
             const float* __restrict__ W_ih,
             const float* __restrict__ W_hh,
             const float* __restrict__ b_ih,
             const float* __restrict__ b_hh,
             const float* __restrict__ out_W,
             const float* __restrict__ out_b,
             const float* __restrict__ wh_W,
             const float* __restrict__ ws_W,
             const float* __restrict__ wx_W,
             const float* __restrict__ wx_b,
             float* __restrict__ out, int out_size) {
    __shared__ __align__(16) float sh_h[H];   // h_new
    __shared__ __align__(16) float sh_a[H];   // attn_applied
    __shared__ __align__(16) float sh_f[H];   // ff
    __shared__ float sh_aw[S];                // softmax weights (chunk blocks)
    __shared__ float sh_m[NWARP], sh_s[NWARP];

    const int tid  = threadIdx.x;
    const int bid  = blockIdx.x;
    const int lane = tid & 31;
    const int wid  = tid >> 5;
    const int gw   = bid * NWARP + wid;

    unsigned barflag = g_flags[bid];          // own flag: race-free entry read

    const int token = idx[0];
    const float* erow = emb + (size_t)token * H;

    // ---- Phase 0: GRU gate pre-activations (3072 warp-dots) ----
    for (int t = wid * NB + bid; t < 3 * H; t += GWARPS) {
        const float* wrow = W_ih + (size_t)t * 2 * H;
        float gi = warp_dot4(wrow, erow, H4) + warp_dot4(wrow + H, trigger, H4);
        float gh = warp_dot4(W_hh + (size_t)t * H, hidden, H4);
        if (lane == 0) {
            g_gi[t] = gi + __ldg(b_ih + t);
            g_gh[t] = gh + __ldg(b_hh + t);
        }
    }
    grid_bar(++barflag);

    // ---- Phase 1: h_new (redundant per block, into smem) + q = attn_W @ h ----
    for (int j = tid; j < H; j += TPB) {
        float gr = g_gi[j] + g_gh[j];
        float gz = g_gi[H + j] + g_gh[H + j];
        float r = sigmoidf_(gr);
        float z = sigmoidf_(gz);
        float n = tanhf(g_gi[2 * H + j] + r * g_gh[2 * H + j]);
        float hn = (1.f - z) * n + z * __ldg(hidden + j);
        sh_h[j] = hn;
        if (bid == 0 && (V + E + j) < out_size) out[V + E + j] = hn;
    }
    __syncthreads();
    for (int r = wid * NB + bid; r < H; r += GWARPS) {
        float v = warp_dot4(attn_W + (size_t)r * H, sh_h, H4);
        if (lane == 0) g_q[r] = v;
    }
    grid_bar(++barflag);

    // ---- Phase 2: scores = enc @ q ----
    for (int r = wid * NB + bid; r < S; r += GWARPS) {
        float v = warp_dot4(enc + (size_t)r * H, g_q, H4);
        if (lane == 0) g_scores[r] = v;
    }
    grid_bar(++barflag);

    // ---- Phase 3: (chunk blocks) redundant softmax + attn/pg chunk partials ----
    if (bid < NCHUNK) {
        float v = (tid < S) ? g_scores[tid] : -3.4e38f;
        float m = blockReduceMax(v);
        float e = (tid < S) ? expf(v - m) : 0.f;
        float sum = blockReduceSum(e);
        if (tid < S) sh_aw[tid] = e / sum;
        __syncthreads();
        if (bid == 0 && tid < S && (V + E + H + tid) < out_size)
            out[V + E + H + tid] = sh_aw[tid];
        const int c = bid;
        for (int j = tid; j < H; j += TPB) {
            float acc = 0.f, accp = 0.f;
#pragma unroll
            for (int k = 0; k < SPC; k++) {
                int s = c * SPC + k;
                float w = sh_aw[s];
                acc = fmaf(w, __ldg(enc + (size_t)s * H + j), acc);
                if (j < E) accp = fmaf(w, __ldg(pg_mat + (size_t)s * E + j), accp);
            }
            g_attn_part[c][j] = acc;
            if (j < E) g_pg_part[c][j] = accp;
        }
    }
    grid_bar(++barflag);

    // ---- Phase 4: attn_applied + p_gen (redundant per block) + pg tail + ff ----
    float pgen;
    {
        float val = 0.f;
        for (int j = tid; j < H; j += TPB) {
            float a = 0.f;
#pragma unroll
            for (int c = 0; c < NCHUNK; c++) a += g_attn_part[c][j];
            sh_a[j] = a;
            val += __ldg(wh_W + j) * a + __ldg(ws_W + j) * sh_h[j]
                 + __ldg(wx_W + j) * erow[j];
        }
        float t = blockReduceSum(val);   // also fences sh_a writes for the block
        pgen = sigmoidf_(t + __ldg(wx_b));
    }
    if (bid == 0) {
        for (int j = tid; j < E; j += TPB) {
            float p = 0.f;
#pragma unroll
            for (int c = 0; c < NCHUNK; c++) p += g_pg_part[c][j];
            if ((V + j) < out_size) out[V + j] = logf(p * (1.f - pgen));
        }
    }
    for (int r = wid * NB + bid; r < H; r += GWARPS) {
        const float* row = comb_W + (size_t)r * 2 * H;
        float v = warp_dot4(row, sh_h, H4) + warp_dot4(row + H, sh_a, H4);
        if (lane == 0) g_ff[r] = fmaxf(v + __ldg(comb_b + r), 0.f);
    }
    grid_bar(++barflag);

    // ---- Phase 5: logits (HBM-bound, 205 MB) + online (max,sum) partials ----
    for (int j = tid; j < H; j += TPB) sh_f[j] = g_ff[j];
    __syncthreads();
    {
        float m_run = -INFINITY, s_run = 0.f;
        for (int j = gw; j < V; j += GWARPS) {
            float l = warp_dot4(out_W + (size_t)j * H, sh_f, H4) + __ldg(out_b + j);
            if (lane == 0) g_logits[j] = l;
            float mn = fmaxf(m_run, l);
            s_run = s_run * expf(m_run - mn) + expf(l - mn);
            m_run = mn;
        }
        if (lane == 0) { sh_m[wid] = m_run; sh_s[wid] = s_run; }
        __syncthreads();
        if (tid == 0) {
            float mb = -INFINITY;
#pragma unroll
            for (int k = 0; k < NWARP; k++) mb = fmaxf(mb, sh_m[k]);
            float sb = 0.f;
#pragma unroll
            for (int k = 0; k < NWARP; k++) sb += sh_s[k] * expf(sh_m[k] - mb);
            g_maxpart[bid] = mb;
            g_sumpart[bid] = sb;
        }
    }
    grid_bar(++barflag);

    // ---- Phase 6: combine 148 (m,s) pairs (redundant) + write vocab logprobs ----
    {
        float m = (tid < NB) ? g_maxpart[tid] : -INFINITY;
        float gm = blockReduceMax(m);
        float contrib = (tid < NB) ? g_sumpart[tid] * expf(g_maxpart[tid] - gm) : 0.f;
        float tot = blockReduceSum(contrib);
        float logc = gm + logf(tot) - logf(pgen);
        int j = bid * TPB + tid;
        if (j < V) out[j] = g_logits[j] - logc;
    }
}

// ---------------- launch ----------------
extern "C" void kernel_launch(void* const* d_in, const int* in_sizes, int n_in,
                              void* d_out, int out_size) {
    const int*   idx     = (const int*)  d_in[0];
    const float* hidden  = (const float*)d_in[1];
    const float* enc     = (const float*)d_in[2];
    const float* trigger = (const float*)d_in[3];
    const float* pg_mat  = (const float*)d_in[4];
    const float* emb     = (const float*)d_in[5];
    const float* attn_W  = (const float*)d_in[6];
    const float* comb_W  = (const float*)d_in[7];
    const float* comb_b  = (const float*)d_in[8];
    const float* W_ih    = (const float*)d_in[9];
    const float* W_hh    = (const float*)d_in[10];
    const float* b_ih    = (const float*)d_in[11];
    const float* b_hh    = (const float*)d_in[12];
    const float* out_W   = (const float*)d_in[13];
    const float* out_b   = (const float*)d_in[14];
    const float* wh_W    = (const float*)d_in[15];
    const float* ws_W    = (const float*)d_in[16];
    const float* wx_W    = (const float*)d_in[17];
    const float* wx_b    = (const float*)d_in[18];
    float* out = (float*)d_out;

    (void)in_sizes; (void)n_in;

    decoder_step<<<NB, TPB>>>(idx, hidden, enc, trigger, pg_mat, emb, attn_W,
                              comb_W, comb_b, W_ih, W_hh, b_ih, b_hh,
                              out_W, out_b, wh_W, ws_W, wx_W, wx_b,
                              out, out_size);
}

// round 6
// speedup vs baseline: 1.5476x; 1.1105x over previous
#include <cuda_runtime.h>
#include <math.h>

#define H 1024
#define H4 256          // H/4 (float4 count)
#define V 50000
#define E 602
#define S 400
#define NB 148          // blocks == SMs (B200)
#define TPB 1024
#define NWARP 32        // TPB/32
#define GWARPS (NB*NWARP)   // 4736
#define NCHUNK 16
#define SPC 25          // S / NCHUNK

// ---------------- scratch (static device globals; no allocs) ----------------
__device__ float g_gi[3*H];
__device__ float g_gh[3*H];
__device__ float g_q[H];
__device__ float g_scores[S];
__device__ float g_attn_part[NCHUNK][H];
__device__ float g_pg_part[NCHUNK][E];
__device__ float g_ff[H];
__device__ float g_logits[V];
__device__ float g_maxpart[NB];
__device__ float g_sumpart[NB];
__device__ volatile unsigned g_flags[NB];   // zero-initialized; monotonic across replays

// ---------------- helpers ----------------
__device__ __forceinline__ float warpReduceSum(float v) {
#pragma unroll
    for (int o = 16; o > 0; o >>= 1) v += __shfl_xor_sync(0xffffffffu, v, o);
    return v;
}
__device__ __forceinline__ float warpReduceMax(float v) {
#pragma unroll
    for (int o = 16; o > 0; o >>= 1) v = fmaxf(v, __shfl_xor_sync(0xffffffffu, v, o));
    return v;
}
__device__ __forceinline__ float blockReduceSum(float v) {
    __shared__ float sh[33];
    __syncthreads();
    int lane = threadIdx.x & 31, wid = threadIdx.x >> 5;
    v = warpReduceSum(v);
    if (lane == 0) sh[wid] = v;
    __syncthreads();
    float r = (threadIdx.x < NWARP) ? sh[threadIdx.x] : 0.f;
    if (wid == 0) {
        r = warpReduceSum(r);
        if (lane == 0) sh[32] = r;
    }
    __syncthreads();
    return sh[32];
}
__device__ __forceinline__ float blockReduceMax(float v) {
    __shared__ float sh[33];
    __syncthreads();
    int lane = threadIdx.x & 31, wid = threadIdx.x >> 5;
    v = warpReduceMax(v);
    if (lane == 0) sh[wid] = v;
    __syncthreads();
    float r = (threadIdx.x < NWARP) ? sh[threadIdx.x] : -3.4e38f;
    if (wid == 0) {
        r = warpReduceMax(r);
        if (lane == 0) sh[32] = r;
    }
    __syncthreads();
    return sh[32];
}

// warp-collective dot of 4*n4 floats; result broadcast to all lanes.
__device__ __forceinline__ float warp_dot4(const float* __restrict__ a,
                                           const float* __restrict__ b, int n4) {
    const float4* a4 = reinterpret_cast<const float4*>(a);
    const float4* b4 = reinterpret_cast<const float4*>(b);
    int lane = threadIdx.x & 31;
    float s = 0.f;
#pragma unroll 8
    for (int k = lane; k < n4; k += 32) {
        float4 x = a4[k];
        float4 y = b4[k];
        s = fmaf(x.x, y.x, fmaf(x.y, y.y, fmaf(x.z, y.z, fmaf(x.w, y.w, s))));
    }
    return warpReduceSum(s);
}

__device__ __forceinline__ float sigmoidf_(float x) { return 1.f / (1.f + expf(-x)); }

// flat grid barrier: each block publishes its own monotonic flag; 148 threads
// poll one flag each. Flags persist across graph replays (each block reads only
// its OWN flag at entry, which only itself writes -> race-free).
__device__ __forceinline__ void grid_bar(unsigned myflag) {
    __syncthreads();
    if (threadIdx.x == 0) {
        __threadfence();
        g_flags[blockIdx.x] = myflag;
    }
    if (threadIdx.x < NB) {
        while (g_flags[threadIdx.x] < myflag) { }
    }
    __syncthreads();
}

// ---------------- the single persistent kernel ----------------
__global__ void __launch_bounds__(TPB, 1)
decoder_step(const int* __restrict__ idx,
             const float* __restrict__ hidden,
             const float* __restrict__ enc,
             const float* __restrict__ trigger,
             const float* __restrict__ pg_mat,
             const float* __restrict__ emb,
             const float* __restrict__ attn_W,
             const float* __restrict__ comb_W,
             const float* __restrict__ comb_b,
             const float* __restrict__ W_ih,
             const float* __restrict__ W_hh,
             const float* __restrict__ b_ih,
             const float* __restrict__ b_hh,
             const float* __restrict__ out_W,
             const float* __restrict__ out_b,
             const float* __restrict__ wh_W,
             const float* __restrict__ ws_W,
             const float* __restrict__ wx_W,
             const float* __restrict__ wx_b,
             float* __restrict__ out, int out_size) {
    __shared__ __align__(16) float sh_h[H];   // h_new
    __shared__ __align__(16) float sh_a[H];   // attn_applied
    __shared__ __align__(16) float sh_f[H];   // ff
    __shared__ float sh_aw[S];                // softmax weights (chunk blocks)
    __shared__ float sh_m[NWARP], sh_s[NWARP];

    const int tid  = threadIdx.x;
    const int bid  = blockIdx.x;
    const int lane = tid & 31;
    const int wid  = tid >> 5;
    const int gw   = bid * NWARP + wid;

    unsigned barflag = g_flags[bid];          // own flag: race-free entry read

    const int token = idx[0];
    const float* erow = emb + (size_t)token * H;

    // ---- Phase 0: GRU gate pre-activations (3072 warp-dots) ----
    for (int t = wid * NB + bid; t < 3 * H; t += GWARPS) {
        const float* wrow = W_ih + (size_t)t * 2 * H;
        float gi = warp_dot4(wrow, erow, H4) + warp_dot4(wrow + H, trigger, H4);
        float gh = warp_dot4(W_hh + (size_t)t * H, hidden, H4);
        if (lane == 0) {
            g_gi[t] = gi + __ldg(b_ih + t);
            g_gh[t] = gh + __ldg(b_hh + t);
        }
    }
    grid_bar(++barflag);

    // ---- Phase 1: h_new (redundant per block, into smem) + q = attn_W @ h ----
    for (int j = tid; j < H; j += TPB) {
        float gr = g_gi[j] + g_gh[j];
        float gz = g_gi[H + j] + g_gh[H + j];
        float r = sigmoidf_(gr);
        float z = sigmoidf_(gz);
        float n = tanhf(g_gi[2 * H + j] + r * g_gh[2 * H + j]);
        float hn = (1.f - z) * n + z * __ldg(hidden + j);
        sh_h[j] = hn;
        if (bid == 0 && (V + E + j) < out_size) out[V + E + j] = hn;
    }
    __syncthreads();
    for (int r = wid * NB + bid; r < H; r += GWARPS) {
        float v = warp_dot4(attn_W + (size_t)r * H, sh_h, H4);
        if (lane == 0) g_q[r] = v;
    }
    grid_bar(++barflag);

    // ---- Phase 2: scores = enc @ q ----
    for (int r = wid * NB + bid; r < S; r += GWARPS) {
        float v = warp_dot4(enc + (size_t)r * H, g_q, H4);
        if (lane == 0) g_scores[r] = v;
    }
    grid_bar(++barflag);

    // ---- Phase 3: (chunk blocks) redundant softmax + attn/pg chunk partials ----
    if (bid < NCHUNK) {
        float v = (tid < S) ? g_scores[tid] : -3.4e38f;
        float m = blockReduceMax(v);
        float e = (tid < S) ? expf(v - m) : 0.f;
        float sum = blockReduceSum(e);
        if (tid < S) sh_aw[tid] = e / sum;
        __syncthreads();
        if (bid == 0 && tid < S && (V + E + H + tid) < out_size)
            out[V + E + H + tid] = sh_aw[tid];
        const int c = bid;
        for (int j = tid; j < H; j += TPB) {
            float acc = 0.f, accp = 0.f;
#pragma unroll
            for (int k = 0; k < SPC; k++) {
                int s = c * SPC + k;
                float w = sh_aw[s];
                acc = fmaf(w, __ldg(enc + (size_t)s * H + j), acc);
                if (j < E) accp = fmaf(w, __ldg(pg_mat + (size_t)s * E + j), accp);
            }
            g_attn_part[c][j] = acc;
            if (j < E) g_pg_part[c][j] = accp;
        }
    }
    grid_bar(++barflag);

    // ---- Phase 4: attn_applied + p_gen (redundant per block) + pg tail + ff ----
    float pgen;
    {
        float val = 0.f;
        for (int j = tid; j < H; j += TPB) {
            float a = 0.f;
#pragma unroll
            for (int c = 0; c < NCHUNK; c++) a += g_attn_part[c][j];
            sh_a[j] = a;
            val += __ldg(wh_W + j) * a + __ldg(ws_W + j) * sh_h[j]
                 + __ldg(wx_W + j) * erow[j];
        }
        float t = blockReduceSum(val);   // also fences sh_a writes for the block
        pgen = sigmoidf_(t + __ldg(wx_b));
    }
    if (bid == 0) {
        for (int j = tid; j < E; j += TPB) {
            float p = 0.f;
#pragma unroll
            for (int c = 0; c < NCHUNK; c++) p += g_pg_part[c][j];
            if ((V + j) < out_size) out[V + j] = logf(p * (1.f - pgen));
        }
    }
    for (int r = wid * NB + bid; r < H; r += GWARPS) {
        const float* row = comb_W + (size_t)r * 2 * H;
        float v = warp_dot4(row, sh_h, H4) + warp_dot4(row + H, sh_a, H4);
        if (lane == 0) g_ff[r] = fmaxf(v + __ldg(comb_b + r), 0.f);
    }
    grid_bar(++barflag);

    // ---- Phase 5: logits (HBM-bound, 205 MB) + online (max,sum) partials ----
    for (int j = tid; j < H; j += TPB) sh_f[j] = g_ff[j];
    __syncthreads();
    {
        float m_run = -INFINITY, s_run = 0.f;
        for (int j = gw; j < V; j += GWARPS) {
            float l = warp_dot4(out_W + (size_t)j * H, sh_f, H4) + __ldg(out_b + j);
            if (lane == 0) g_logits[j] = l;
            float mn = fmaxf(m_run, l);
            s_run = s_run * expf(m_run - mn) + expf(l - mn);
            m_run = mn;
        }
        if (lane == 0) { sh_m[wid] = m_run; sh_s[wid] = s_run; }
        __syncthreads();
        if (tid == 0) {
            float mb = -INFINITY;
#pragma unroll
            for (int k = 0; k < NWARP; k++) mb = fmaxf(mb, sh_m[k]);
            float sb = 0.f;
#pragma unroll
            for (int k = 0; k < NWARP; k++) sb += sh_s[k] * expf(sh_m[k] - mb);
            g_maxpart[bid] = mb;
            g_sumpart[bid] = sb;
        }
    }
    grid_bar(++barflag);

    // ---- Phase 6: combine 148 (m,s) pairs (redundant) + write vocab logprobs ----
    {
        float m = (tid < NB) ? g_maxpart[tid] : -INFINITY;
        float gm = blockReduceMax(m);
        float contrib = (tid < NB) ? g_sumpart[tid] * expf(g_maxpart[tid] - gm) : 0.f;
        float tot = blockReduceSum(contrib);
        float logc = gm + logf(tot) - logf(pgen);
        int j = bid * TPB + tid;
        if (j < V) out[j] = g_logits[j] - logc;
    }
}

// ---------------- launch ----------------
extern "C" void kernel_launch(void* const* d_in, const int* in_sizes, int n_in,
                              void* d_out, int out_size) {
    const int*   idx     = (const int*)  d_in[0];
    const float* hidden  = (const float*)d_in[1];
    const float* enc     = (const float*)d_in[2];
    const float* trigger = (const float*)d_in[3];
    const float* pg_mat  = (const float*)d_in[4];
    const float* emb     = (const float*)d_in[5];
    const float* attn_W  = (const float*)d_in[6];
    const float* comb_W  = (const float*)d_in[7];
    const float* comb_b  = (const float*)d_in[8];
    const float* W_ih    = (const float*)d_in[9];
    const float* W_hh    = (const float*)d_in[10];
    const float* b_ih    = (const float*)d_in[11];
    const float* b_hh    = (const float*)d_in[12];
    const float* out_W   = (const float*)d_in[13];
    const float* out_b   = (const float*)d_in[14];
    const float* wh_W    = (const float*)d_in[15];
    const float* ws_W    = (const float*)d_in[16];
    const float* wx_W    = (const float*)d_in[17];
    const float* wx_b    = (const float*)d_in[18];
    float* out = (float*)d_out;

    (void)in_sizes; (void)n_in;

    decoder_step<<<NB, TPB>>>(idx, hidden, enc, trigger, pg_mat, emb, attn_W,
                              comb_W, comb_b, W_ih, W_hh, b_ih, b_hh,
                              out_W, out_b, wh_W, ws_W, wx_W, wx_b,
                              out, out_size);
}